// round 14
// baseline (speedup 1.0000x reference)
#include <cuda_runtime.h>
#include <math.h>
#include <stdint.h>

#define BQ   4
#define CCH  3
#define HH   512
#define WW   512
#define NPL  32
#define TW   32            // tile width  (8 threads x 4 px)
#define TH   16            // tile height
#define HALO_L 16          // left halo (16B-aligned quads)
#define SWP  64            // 16 quads per row
#define SH   (TH + 30)     // 46 halo rows
#define QPR  16
#define NQ   (SH * QPR)    // 736 quads per channel

#define NTILE_X 16
#define NTILE_Y 32
#define NTILES  (NTILE_X * NTILE_Y * BQ)   // 2048
#define NCTA    740                        // 5 CTAs/SM x 148 SMs

#define SYMI(d) ((d) < 16 ? (d) : 30 - (d))

__device__ constexpr float midp(int i) {
    return ((float)(i * (50.0 / 31.0)) + (float)((i + 1) * (50.0 / 31.0))) * 0.5f;
}

__device__ __forceinline__ void cp_async16(uint32_t daddr, const void* src, int srcsize) {
    asm volatile("cp.async.cg.shared.global [%0], [%1], 16, %2;"
                 :: "r"(daddr), "l"(src), "r"(srcsize) : "memory");
}
__device__ __forceinline__ void cp_commit() {
    asm volatile("cp.async.commit_group;" ::: "memory");
}
template <int N>
__device__ __forceinline__ void cp_wait() {
    asm volatile("cp.async.wait_group %0;" :: "n"(N) : "memory");
}

__global__ void __launch_bounds__(128, 5)
defocus_kernel(const float* __restrict__ sharp,
               const float* __restrict__ coc,
               float* __restrict__ out) {
    __shared__ float tile[CCH][SH][SWP];   // 35328 B (rotating channel bufs)
    __shared__ float wt[16][32];           // transposed folded table (bank=plane)
    __shared__ float fscr[2][4][4][SWP];   // parity-double-buffered folds: 8192 B

    const int tx  = threadIdx.x;           // 0..7
    const int ty  = threadIdx.y;           // 0..15
    const int tid = ty * 8 + tx;
    const int wk  = tid >> 5;              // warp 0..3 (covers ty = 4wk..4wk+3)
    const int l   = tid & 31;              // lane
    const int jj1 = l >> 4;                // fold rows handled: jj1 and jj1+2
    const int chk = l & 15;                // 4-float chunk within row

    // ---- weight table phase 1: unnormalized entries ----
    const double step = 50.0 / 31.0;
#pragma unroll
    for (int idx = tid; idx < NPL * 16; idx += 128) {
        const int i = idx & 31;            // plane
        const int j = idx >> 5;            // folded tap (15 = center)
        const float cocf = (float)(i * step);
        float e;
        if (cocf < 0.5f) {
            e = (j == 15) ? 1.0f : 0.0f;
        } else {
            double cd = (double)cocf;
            int k = (int)(2.0 * cd + 1.0);
            if (!(k & 1)) k++;
            if (k > 31) k = 31;
            const int half = k >> 1;
            const int d = 15 - j;
            if (d > half) {
                e = 0.0f;
            } else {
                double sg = cd / 2.355;
                float inv2 = (float)(1.0 / (2.0 * sg * sg));
                e = expf(-(float)(d * d) * inv2);
            }
        }
        wt[j][i] = e;
    }

#define ISSUE_CH(t_, c_)                                                        \
    do {                                                                        \
        int bx_ = (t_) & (NTILE_X - 1);                                         \
        int by_ = ((t_) >> 4) & (NTILE_Y - 1);                                  \
        int bb_ = (t_) >> 9;                                                    \
        int xo_ = bx_ * TW, yo_ = by_ * TH;                                     \
        const float* sc_ = sharp + ((size_t)(bb_ * CCH + (c_))) * HH * WW;      \
        _Pragma("unroll")                                                       \
        for (int u_ = 0; u_ < 6; u_++) {                                        \
            int q_ = u_ * 128 + tid;                                            \
            if (q_ < NQ) {                                                      \
                int r_ = q_ >> 4;                                               \
                int qq_ = q_ & 15;                                              \
                int gx_ = xo_ - HALO_L + 4 * qq_;                               \
                int gy_ = yo_ - 15 + r_;                                        \
                bool ok_ = ((unsigned)gx_ <= (unsigned)(WW - 4)) &&             \
                           ((unsigned)gy_ <  (unsigned)HH);                     \
                const float* s_ = sc_ + (ok_ ? (gy_ * WW + gx_) : 0);           \
                uint32_t d_ = (uint32_t)__cvta_generic_to_shared(               \
                                  &tile[c_][r_][4 * qq_]);                      \
                cp_async16(d_, s_, ok_ ? 16 : 0);                               \
            }                                                                   \
        }                                                                       \
    } while (0)

// warp-cooperative fold of row-pair set s_ into parity buffer pb_
#define FOLD(tc_, s_, pb_)                                                      \
    do {                                                                        \
        const float* basep_ = (tc_) + 4 * chk;                                  \
        _Pragma("unroll")                                                       \
        for (int jj_ = jj1; jj_ < 4; jj_ += 2) {                                \
            const int rA_ = 4 * wk + jj_ + (s_);                                \
            const int rB_ = 4 * wk + jj_ + 30 - (s_);                           \
            float4 qa_ = *(const float4*)(basep_ + rA_ * SWP);                  \
            float4 qb_ = *(const float4*)(basep_ + rB_ * SWP);                  \
            float4 f_;                                                          \
            f_.x = qa_.x + qb_.x; f_.y = qa_.y + qb_.y;                         \
            f_.z = qa_.z + qb_.z; f_.w = qa_.w + qb_.w;                         \
            *(float4*)&fscr[pb_][wk][jj_][4 * chk] = f_;                        \
        }                                                                       \
    } while (0)

    // ---- prologue: first tile's 3 channel groups in flight ----
    const int t0 = blockIdx.x;
    ISSUE_CH(t0, 0); cp_commit();
    ISSUE_CH(t0, 1); cp_commit();
    ISSUE_CH(t0, 2); cp_commit();

    __syncthreads();                       // phase-1 wt writes visible

    // ---- weight table phase 2: normalize plane columns (bank = tid) ----
    if (tid < NPL) {
        float s = wt[15][tid];
#pragma unroll
        for (int j = 0; j < 15; j++) s += 2.0f * wt[j][tid];
        const float inv = 1.0f / s;
#pragma unroll
        for (int j = 0; j < 16; j++) wt[j][tid] *= inv;
    }
    __syncthreads();

    // ---- persistent tile loop ----
    for (int t = t0; t < NTILES; t += NCTA) {
        const int bx = t & (NTILE_X - 1);
        const int by = (t >> 4) & (NTILE_Y - 1);
        const int b  = t >> 9;
        const int x0 = bx * TW;
        const int y0 = by * TH;
        const int xA = x0 + 4 * tx;
        const int y  = y0 + ty;

        // plane bucketing (immediate midpoints)
        const float4 c4 = *(const float4*)(coc + ((size_t)b * HH + y) * WW + xA);
        int p0 = 0, p1 = 0, p2 = 0, p3 = 0;
#pragma unroll
        for (int i = 0; i < 31; i++) {
            const float m = midp(i);
            p0 += c4.x > m; p1 += c4.y > m; p2 += c4.z > m; p3 += c4.w > m;
        }

        // symmetric half-kernels into regs (conflict-free LDS: bank = plane)
        float wA[16], wB[16], wC[16], wD[16];
#pragma unroll
        for (int j = 0; j < 16; j++) {
            wA[j] = wt[j][p0]; wB[j] = wt[j][p1];
            wC[j] = wt[j][p2]; wD[j] = wt[j][p3];
        }

        float* ob = out + (size_t)b * CCH * HH * WW;
        const int tn = t + NCTA;           // next tile for this CTA

#pragma unroll 1
        for (int c = 0; c < CCH; c++) {
            cp_wait<2>();                  // exactly the (t,c) group retires
            __syncthreads();               // all threads' copies visible

            const float* tc = &tile[c][0][0];
            float accA = 0.f, accB = 0.f, accC = 0.f, accD = 0.f;

            FOLD(tc, 0, 0);                // prologue fold s=0 -> buf 0

#pragma unroll 2
            for (int s = 0; s < 16; s++) {
                // iteration-top sync covers: RAW fold(s)->H(s) and
                // WAR H(s-1)->fold(s+1) (s-1, s+1 share parity).
                __syncwarp();
                if (s < 15) FOLD(tc, s + 1, (s + 1) & 1);

                const float hs = (s == 15) ? 0.5f : 1.0f;
                const float gA = wt[s][p0] * hs;
                const float gB = wt[s][p1] * hs;
                const float gC = wt[s][p2] * hs;
                const float gD = wt[s][p3] * hs;

                const float* fr = &fscr[s & 1][wk][ty & 3][4 * tx];
                float4 Fp = *(const float4*)fr;
                float a = 0.f, bb2 = 0.f, cc2 = 0.f, d = 0.f;
#pragma unroll
                for (int m = 1; m <= 8; m++) {
                    float4 Fc = *(const float4*)(fr + 4 * m);
                    const float fp[4] = {Fp.x, Fp.y, Fp.z, Fp.w};
                    const float fc[4] = {Fc.x, Fc.y, Fc.z, Fc.w};
#pragma unroll
                    for (int tt = 0; tt < 4; tt++) {
                        const int tau = 4 * (m - 1) + tt;
                        if (tau <= 30) {
                            const int sj = SYMI(tau);
                            a   += wA[sj] * ((tt < 3) ? fp[tt + 1] : fc[0]);
                            bb2 += wB[sj] * ((tt < 2) ? fp[tt + 2] : fc[tt - 2]);
                            cc2 += wC[sj] * ((tt < 1) ? fp[tt + 3] : fc[tt - 1]);
                            d   += wD[sj] * fc[tt];
                        }
                    }
                    Fp = Fc;
                }
                accA += gA * a;
                accB += gB * bb2;
                accC += gC * cc2;
                accD += gD * d;
            }
            *(float4*)(ob + ((size_t)c * HH + y) * WW + xA) =
                make_float4(accA, accB, accC, accD);

            __syncthreads();               // buffer c free for refill
            if (tn < NTILES) ISSUE_CH(tn, c);
            cp_commit();                   // empty group keeps wait<2> uniform
        }
    }
#undef ISSUE_CH
#undef FOLD
}

// ---------------------------------------------------------------------------
extern "C" void kernel_launch(void* const* d_in, const int* in_sizes, int n_in,
                              void* d_out, int out_size) {
    const float* sharp = (const float*)d_in[0];
    const float* coc   = (const float*)d_in[1];
    if (n_in >= 2 && in_sizes[0] == BQ * HH * WW && in_sizes[1] == BQ * CCH * HH * WW) {
        sharp = (const float*)d_in[1];   // defensive input-order swap
        coc   = (const float*)d_in[0];
    }
    float* out = (float*)d_out;

    dim3 grid(NCTA, 1, 1);               // persistent: 5 CTAs/SM x 148 SMs
    dim3 block(8, 16);
    defocus_kernel<<<grid, block>>>(sharp, coc, out);
}

// round 15
// speedup vs baseline: 1.5435x; 1.5435x over previous
#include <cuda_runtime.h>
#include <math.h>
#include <stdint.h>

#define BQ   4
#define CCH  3
#define HH   512
#define WW   512
#define NPL  32
#define TW   32            // tile width  (8 threads x 4 px)
#define TH   16            // tile height
#define HALO_L 16          // left halo (16B-aligned quads)
#define SWP  64            // 16 quads per row
#define SH   (TH + 30)     // 46 halo rows
#define QPR  16
#define NQ   (SH * QPR)    // 736 quads per channel

#define NTILE_X 16
#define NTILE_Y 32
#define NTILES  (NTILE_X * NTILE_Y * BQ)   // 2048
#define NCTA    740                        // 5 CTAs/SM x 148 SMs

#define SYMI(d) ((d) < 16 ? (d) : 30 - (d))

__device__ constexpr float midp(int i) {
    return ((float)(i * (50.0 / 31.0)) + (float)((i + 1) * (50.0 / 31.0))) * 0.5f;
}

__device__ __forceinline__ void cp_async16(uint32_t daddr, const void* src, int srcsize) {
    asm volatile("cp.async.cg.shared.global [%0], [%1], 16, %2;"
                 :: "r"(daddr), "l"(src), "r"(srcsize) : "memory");
}
__device__ __forceinline__ void cp_commit() {
    asm volatile("cp.async.commit_group;" ::: "memory");
}
template <int N>
__device__ __forceinline__ void cp_wait() {
    asm volatile("cp.async.wait_group %0;" :: "n"(N) : "memory");
}

__global__ void __launch_bounds__(128, 5)
defocus_kernel(const float* __restrict__ sharp,
               const float* __restrict__ coc,
               float* __restrict__ out) {
    __shared__ float tile[CCH][SH][SWP];   // 35328 B (rotating channel bufs)
    __shared__ float wt[16][32];           // transposed folded table (bank=plane)
    __shared__ float fscr[4][4][SWP];      // per-warp folded rows: 4096 B

    const int tx  = threadIdx.x;           // 0..7
    const int ty  = threadIdx.y;           // 0..15
    const int tid = ty * 8 + tx;
    const int wk  = tid >> 5;              // warp 0..3  (covers ty = 4wk..4wk+3)
    const int l   = tid & 31;              // lane
    const int jj1 = l >> 4;                // fold rows handled: jj1 and jj1+2
    const int chk = l & 15;                // 4-float chunk within row

    // ---- weight table phase 1: unnormalized entries ----
    const double step = 50.0 / 31.0;
#pragma unroll
    for (int idx = tid; idx < NPL * 16; idx += 128) {
        const int i = idx & 31;            // plane
        const int j = idx >> 5;            // folded tap (15 = center)
        const float cocf = (float)(i * step);
        float e;
        if (cocf < 0.5f) {
            e = (j == 15) ? 1.0f : 0.0f;
        } else {
            double cd = (double)cocf;
            int k = (int)(2.0 * cd + 1.0);
            if (!(k & 1)) k++;
            if (k > 31) k = 31;
            const int half = k >> 1;
            const int d = 15 - j;
            if (d > half) {
                e = 0.0f;
            } else {
                double sg = cd / 2.355;
                float inv2 = (float)(1.0 / (2.0 * sg * sg));
                e = expf(-(float)(d * d) * inv2);
            }
        }
        wt[j][i] = e;
    }

#define ISSUE_CH(t_, c_)                                                        \
    do {                                                                        \
        int bx_ = (t_) & (NTILE_X - 1);                                         \
        int by_ = ((t_) >> 4) & (NTILE_Y - 1);                                  \
        int bb_ = (t_) >> 9;                                                    \
        int xo_ = bx_ * TW, yo_ = by_ * TH;                                     \
        const float* sc_ = sharp + ((size_t)(bb_ * CCH + (c_))) * HH * WW;      \
        _Pragma("unroll")                                                       \
        for (int u_ = 0; u_ < 6; u_++) {                                        \
            int q_ = u_ * 128 + tid;                                            \
            if (q_ < NQ) {                                                      \
                int r_ = q_ >> 4;                                               \
                int qq_ = q_ & 15;                                              \
                int gx_ = xo_ - HALO_L + 4 * qq_;                               \
                int gy_ = yo_ - 15 + r_;                                        \
                bool ok_ = ((unsigned)gx_ <= (unsigned)(WW - 4)) &&             \
                           ((unsigned)gy_ <  (unsigned)HH);                     \
                const float* s_ = sc_ + (ok_ ? (gy_ * WW + gx_) : 0);           \
                uint32_t d_ = (uint32_t)__cvta_generic_to_shared(               \
                                  &tile[c_][r_][4 * qq_]);                      \
                cp_async16(d_, s_, ok_ ? 16 : 0);                               \
            }                                                                   \
        }                                                                       \
    } while (0)

    // ---- prologue: first tile's 3 channel groups in flight ----
    const int t0 = blockIdx.x;
    ISSUE_CH(t0, 0); cp_commit();
    ISSUE_CH(t0, 1); cp_commit();
    ISSUE_CH(t0, 2); cp_commit();

    __syncthreads();                       // phase-1 wt writes visible

    // ---- weight table phase 2: normalize plane columns (bank = tid) ----
    if (tid < NPL) {
        float s = wt[15][tid];
#pragma unroll
        for (int j = 0; j < 15; j++) s += 2.0f * wt[j][tid];
        const float inv = 1.0f / s;
#pragma unroll
        for (int j = 0; j < 16; j++) wt[j][tid] *= inv;
    }
    __syncthreads();

    // ---- persistent tile loop ----
    for (int t = t0; t < NTILES; t += NCTA) {
        const int bx = t & (NTILE_X - 1);
        const int by = (t >> 4) & (NTILE_Y - 1);
        const int b  = t >> 9;
        const int x0 = bx * TW;
        const int y0 = by * TH;
        const int xA = x0 + 4 * tx;
        const int y  = y0 + ty;

        // plane bucketing (immediate midpoints)
        const float4 c4 = *(const float4*)(coc + ((size_t)b * HH + y) * WW + xA);
        int p0 = 0, p1 = 0, p2 = 0, p3 = 0;
#pragma unroll
        for (int i = 0; i < 31; i++) {
            const float m = midp(i);
            p0 += c4.x > m; p1 += c4.y > m; p2 += c4.z > m; p3 += c4.w > m;
        }

        // symmetric half-kernels into regs (conflict-free LDS: bank = plane)
        float wA[16], wB[16], wC[16], wD[16];
#pragma unroll
        for (int j = 0; j < 16; j++) {
            wA[j] = wt[j][p0]; wB[j] = wt[j][p1];
            wC[j] = wt[j][p2]; wD[j] = wt[j][p3];
        }

        float* ob = out + (size_t)b * CCH * HH * WW;
        const int tn = t + NCTA;           // next tile for this CTA

#pragma unroll 1
        for (int c = 0; c < CCH; c++) {
            cp_wait<2>();                  // exactly the (t,c) group retires
            __syncthreads();               // all threads' copies visible

            const float* tc = &tile[c][0][0];
            const float* fr = &fscr[wk][ty & 3][4 * tx];  // this thread's window
            float accA = 0.f, accB = 0.f, accC = 0.f, accD = 0.f;

#pragma unroll 1
            for (int s = 0; s < 16; s++) {
                const float hs = (s == 15) ? 0.5f : 1.0f;
                const float gA = wt[s][p0] * hs;
                const float gB = wt[s][p1] * hs;
                const float gC = wt[s][p2] * hs;
                const float gD = wt[s][p3] * hs;

                // -- warp-cooperative fold of this warp's 4 row-pairs --
                __syncwarp();              // WAR: prior reads of fscr done
                {
                    const float* basep = tc + 4 * chk;
#pragma unroll
                    for (int jj = jj1; jj < 4; jj += 2) {
                        const int rA = 4 * wk + jj + s;
                        const int rB = 4 * wk + jj + 30 - s;
                        float4 qa = *(const float4*)(basep + rA * SWP);
                        float4 qb = *(const float4*)(basep + rB * SWP);
                        float4 f;
                        f.x = qa.x + qb.x; f.y = qa.y + qb.y;
                        f.z = qa.z + qb.z; f.w = qa.w + qb.w;
                        *(float4*)&fscr[wk][jj][4 * chk] = f;
                    }
                }
                __syncwarp();              // RAW: folds visible to warp

                // -- H-pass on the folded row (streaming window) --
                float4 Fp = *(const float4*)fr;
                float a = 0.f, bb2 = 0.f, cc2 = 0.f, d = 0.f;
#pragma unroll
                for (int m = 1; m <= 8; m++) {
                    float4 Fc = *(const float4*)(fr + 4 * m);
                    const float fp[4] = {Fp.x, Fp.y, Fp.z, Fp.w};
                    const float fc[4] = {Fc.x, Fc.y, Fc.z, Fc.w};
#pragma unroll
                    for (int tt = 0; tt < 4; tt++) {
                        const int tau = 4 * (m - 1) + tt;
                        if (tau <= 30) {
                            const int sj = SYMI(tau);
                            a   += wA[sj] * ((tt < 3) ? fp[tt + 1] : fc[0]);
                            bb2 += wB[sj] * ((tt < 2) ? fp[tt + 2] : fc[tt - 2]);
                            cc2 += wC[sj] * ((tt < 1) ? fp[tt + 3] : fc[tt - 1]);
                            d   += wD[sj] * fc[tt];
                        }
                    }
                    Fp = Fc;
                }
                accA += gA * a;
                accB += gB * bb2;
                accC += gC * cc2;
                accD += gD * d;
            }
            *(float4*)(ob + ((size_t)c * HH + y) * WW + xA) =
                make_float4(accA, accB, accC, accD);

            __syncthreads();               // buffer c free for refill
            if (tn < NTILES) ISSUE_CH(tn, c);
            cp_commit();                   // empty group keeps wait<2> uniform
        }
    }
#undef ISSUE_CH
}

// ---------------------------------------------------------------------------
extern "C" void kernel_launch(void* const* d_in, const int* in_sizes, int n_in,
                              void* d_out, int out_size) {
    const float* sharp = (const float*)d_in[0];
    const float* coc   = (const float*)d_in[1];
    if (n_in >= 2 && in_sizes[0] == BQ * HH * WW && in_sizes[1] == BQ * CCH * HH * WW) {
        sharp = (const float*)d_in[1];   // defensive input-order swap
        coc   = (const float*)d_in[0];
    }
    float* out = (float*)d_out;

    dim3 grid(NCTA, 1, 1);               // persistent: 5 CTAs/SM x 148 SMs
    dim3 block(8, 16);
    defocus_kernel<<<grid, block>>>(sharp, coc, out);
}

// round 16
// speedup vs baseline: 1.5477x; 1.0028x over previous
#include <cuda_runtime.h>
#include <math.h>
#include <stdint.h>

#define BQ   4
#define CCH  3
#define HH   512
#define WW   512
#define NPL  32
#define TW   32            // tile width  (8 threads x 4 px)
#define TH   16            // tile height
#define HALO_L 16          // left halo (16B-aligned quads)
#define SWP  64            // 16 quads per row
#define SH   (TH + 30)     // 46 halo rows
#define QPR  16
#define NQ   (SH * QPR)    // 736 quads per channel

#define NTILE_X 16
#define NTILE_Y 32
#define NTILES  (NTILE_X * NTILE_Y * BQ)   // 2048
#define NCTA    740                        // 5 CTAs/SM x 148 SMs

#define SYMI(d) ((d) < 16 ? (d) : 30 - (d))

__device__ constexpr float midp(int i) {
    return ((float)(i * (50.0 / 31.0)) + (float)((i + 1) * (50.0 / 31.0))) * 0.5f;
}

__device__ __forceinline__ void cp_async16(uint32_t daddr, const void* src, int srcsize) {
    asm volatile("cp.async.cg.shared.global [%0], [%1], 16, %2;"
                 :: "r"(daddr), "l"(src), "r"(srcsize) : "memory");
}
__device__ __forceinline__ void cp_commit() {
    asm volatile("cp.async.commit_group;" ::: "memory");
}
template <int N>
__device__ __forceinline__ void cp_wait() {
    asm volatile("cp.async.wait_group %0;" :: "n"(N) : "memory");
}

__global__ void __launch_bounds__(128, 5)
defocus_kernel(const float* __restrict__ sharp,
               const float* __restrict__ coc,
               float* __restrict__ out) {
    __shared__ float tile[CCH][SH][SWP];   // 35328 B (rotating channel bufs)
    __shared__ float wt[16][32];           // transposed folded table (bank=plane)
    __shared__ float fscr[2][4][4][SWP];   // double-buffered folds: 8192 B

    const int tx  = threadIdx.x;           // 0..7
    const int ty  = threadIdx.y;           // 0..15
    const int tid = ty * 8 + tx;
    const int wk  = tid >> 5;              // warp 0..3  (covers ty = 4wk..4wk+3)
    const int l   = tid & 31;              // lane
    const int jj1 = l >> 4;                // fold rows handled: jj1 and jj1+2
    const int chk = l & 15;                // 4-float chunk within row

    // ---- weight table phase 1: unnormalized entries ----
    const double step = 50.0 / 31.0;
#pragma unroll
    for (int idx = tid; idx < NPL * 16; idx += 128) {
        const int i = idx & 31;            // plane
        const int j = idx >> 5;            // folded tap (15 = center)
        const float cocf = (float)(i * step);
        float e;
        if (cocf < 0.5f) {
            e = (j == 15) ? 1.0f : 0.0f;
        } else {
            double cd = (double)cocf;
            int k = (int)(2.0 * cd + 1.0);
            if (!(k & 1)) k++;
            if (k > 31) k = 31;
            const int half = k >> 1;
            const int d = 15 - j;
            if (d > half) {
                e = 0.0f;
            } else {
                double sg = cd / 2.355;
                float inv2 = (float)(1.0 / (2.0 * sg * sg));
                e = expf(-(float)(d * d) * inv2);
            }
        }
        wt[j][i] = e;
    }

#define ISSUE_CH(t_, c_)                                                        \
    do {                                                                        \
        int bx_ = (t_) & (NTILE_X - 1);                                         \
        int by_ = ((t_) >> 4) & (NTILE_Y - 1);                                  \
        int bb_ = (t_) >> 9;                                                    \
        int xo_ = bx_ * TW, yo_ = by_ * TH;                                     \
        const float* sc_ = sharp + ((size_t)(bb_ * CCH + (c_))) * HH * WW;      \
        _Pragma("unroll")                                                       \
        for (int u_ = 0; u_ < 6; u_++) {                                        \
            int q_ = u_ * 128 + tid;                                            \
            if (q_ < NQ) {                                                      \
                int r_ = q_ >> 4;                                               \
                int qq_ = q_ & 15;                                              \
                int gx_ = xo_ - HALO_L + 4 * qq_;                               \
                int gy_ = yo_ - 15 + r_;                                        \
                bool ok_ = ((unsigned)gx_ <= (unsigned)(WW - 4)) &&             \
                           ((unsigned)gy_ <  (unsigned)HH);                     \
                const float* s_ = sc_ + (ok_ ? (gy_ * WW + gx_) : 0);           \
                uint32_t d_ = (uint32_t)__cvta_generic_to_shared(               \
                                  &tile[c_][r_][4 * qq_]);                      \
                cp_async16(d_, s_, ok_ ? 16 : 0);                               \
            }                                                                   \
        }                                                                       \
    } while (0)

// warp-cooperative fold of row-pair set s_ into buffer pointed to by dst_
// (dst_ points at this warp's [4][SWP] region)
#define FOLD(tc_, s_, dst_)                                                     \
    do {                                                                        \
        const float* basep_ = (tc_) + 4 * chk;                                  \
        _Pragma("unroll")                                                       \
        for (int jj_ = jj1; jj_ < 4; jj_ += 2) {                                \
            const int rA_ = 4 * wk + jj_ + (s_);                                \
            const int rB_ = 4 * wk + jj_ + 30 - (s_);                           \
            float4 qa_ = *(const float4*)(basep_ + rA_ * SWP);                  \
            float4 qb_ = *(const float4*)(basep_ + rB_ * SWP);                  \
            float4 f_;                                                          \
            f_.x = qa_.x + qb_.x; f_.y = qa_.y + qb_.y;                         \
            f_.z = qa_.z + qb_.z; f_.w = qa_.w + qb_.w;                         \
            *(float4*)((dst_) + jj_ * SWP + 4 * chk) = f_;                      \
        }                                                                       \
    } while (0)

    // ---- prologue: first tile's 3 channel groups in flight ----
    const int t0 = blockIdx.x;
    ISSUE_CH(t0, 0); cp_commit();
    ISSUE_CH(t0, 1); cp_commit();
    ISSUE_CH(t0, 2); cp_commit();

    __syncthreads();                       // phase-1 wt writes visible

    // ---- weight table phase 2: normalize plane columns (bank = tid) ----
    if (tid < NPL) {
        float s = wt[15][tid];
#pragma unroll
        for (int j = 0; j < 15; j++) s += 2.0f * wt[j][tid];
        const float inv = 1.0f / s;
#pragma unroll
        for (int j = 0; j < 16; j++) wt[j][tid] *= inv;
    }
    __syncthreads();

    // ---- persistent tile loop ----
    for (int t = t0; t < NTILES; t += NCTA) {
        const int bx = t & (NTILE_X - 1);
        const int by = (t >> 4) & (NTILE_Y - 1);
        const int b  = t >> 9;
        const int x0 = bx * TW;
        const int y0 = by * TH;
        const int xA = x0 + 4 * tx;
        const int y  = y0 + ty;

        // plane bucketing (immediate midpoints)
        const float4 c4 = *(const float4*)(coc + ((size_t)b * HH + y) * WW + xA);
        int p0 = 0, p1 = 0, p2 = 0, p3 = 0;
#pragma unroll
        for (int i = 0; i < 31; i++) {
            const float m = midp(i);
            p0 += c4.x > m; p1 += c4.y > m; p2 += c4.z > m; p3 += c4.w > m;
        }

        // symmetric half-kernels into regs (conflict-free LDS: bank = plane)
        float wA[16], wB[16], wC[16], wD[16];
#pragma unroll
        for (int j = 0; j < 16; j++) {
            wA[j] = wt[j][p0]; wB[j] = wt[j][p1];
            wC[j] = wt[j][p2]; wD[j] = wt[j][p3];
        }

        float* ob = out + (size_t)b * CCH * HH * WW;
        const int tn = t + NCTA;           // next tile for this CTA

#pragma unroll 1
        for (int c = 0; c < CCH; c++) {
            cp_wait<2>();                  // exactly the (t,c) group retires
            __syncthreads();               // all threads' copies visible
                                           // (also orders fscr reuse across c)

            const float* tc = &tile[c][0][0];
            float* cur = &fscr[0][wk][0][0];
            float* nxt = &fscr[1][wk][0][0];
            const int fro = (ty & 3) * SWP + 4 * tx;   // window offset in buf
            float accA = 0.f, accB = 0.f, accC = 0.f, accD = 0.f;

            FOLD(tc, 0, cur);              // prologue fold s=0

#pragma unroll 1
            for (int s = 0; s < 16; s++) {
                // single sync per iteration:
                //  RAW  fold(s)->H(s)        (fold issued last iteration/prologue)
                //  WAR  H(s-1) reads nxt -> fold(s+1) writes nxt
                __syncwarp();
                if (s < 15) FOLD(tc, s + 1, nxt);

                const float hs = (s == 15) ? 0.5f : 1.0f;
                const float gA = wt[s][p0] * hs;
                const float gB = wt[s][p1] * hs;
                const float gC = wt[s][p2] * hs;
                const float gD = wt[s][p3] * hs;

                const float* fr = cur + fro;
                float4 Fp = *(const float4*)fr;
                float a = 0.f, bb2 = 0.f, cc2 = 0.f, d = 0.f;
#pragma unroll
                for (int m = 1; m <= 8; m++) {
                    float4 Fc = *(const float4*)(fr + 4 * m);
                    const float fp[4] = {Fp.x, Fp.y, Fp.z, Fp.w};
                    const float fc[4] = {Fc.x, Fc.y, Fc.z, Fc.w};
#pragma unroll
                    for (int tt = 0; tt < 4; tt++) {
                        const int tau = 4 * (m - 1) + tt;
                        if (tau <= 30) {
                            const int sj = SYMI(tau);
                            a   += wA[sj] * ((tt < 3) ? fp[tt + 1] : fc[0]);
                            bb2 += wB[sj] * ((tt < 2) ? fp[tt + 2] : fc[tt - 2]);
                            cc2 += wC[sj] * ((tt < 1) ? fp[tt + 3] : fc[tt - 1]);
                            d   += wD[sj] * fc[tt];
                        }
                    }
                    Fp = Fc;
                }
                accA += gA * a;
                accB += gB * bb2;
                accC += gC * cc2;
                accD += gD * d;

                float* tmp = cur; cur = nxt; nxt = tmp;   // swap buffers
            }
            *(float4*)(ob + ((size_t)c * HH + y) * WW + xA) =
                make_float4(accA, accB, accC, accD);

            __syncthreads();               // buffer c free for refill
            if (tn < NTILES) ISSUE_CH(tn, c);
            cp_commit();                   // empty group keeps wait<2> uniform
        }
    }
#undef ISSUE_CH
#undef FOLD
}

// ---------------------------------------------------------------------------
extern "C" void kernel_launch(void* const* d_in, const int* in_sizes, int n_in,
                              void* d_out, int out_size) {
    const float* sharp = (const float*)d_in[0];
    const float* coc   = (const float*)d_in[1];
    if (n_in >= 2 && in_sizes[0] == BQ * HH * WW && in_sizes[1] == BQ * CCH * HH * WW) {
        sharp = (const float*)d_in[1];   // defensive input-order swap
        coc   = (const float*)d_in[0];
    }
    float* out = (float*)d_out;

    dim3 grid(NCTA, 1, 1);               // persistent: 5 CTAs/SM x 148 SMs
    dim3 block(8, 16);
    defocus_kernel<<<grid, block>>>(sharp, coc, out);
}